// round 7
// baseline (speedup 1.0000x reference)
#include <cuda_runtime.h>
#include <cstdint>

#define NN 100000
#define NE 1600000
#define NF 128
#define HD 64

// ---------------- scratch (no allocs allowed) ----------------
__device__ __align__(16) float g_dinv[NN];
__device__ __align__(16) float g_t  [NN * HD];   // (h @ W) * dinv[row]
__device__ __align__(16) float g_h  [NN * HD];   // layer output
__device__ int g_deg[NN];
__device__ int g_cursor[NN];
__device__ int g_rowstart[NN + 1];
__device__ int g_csr[NE];
__device__ float g_loss;
__device__ int   g_lsum;

// ---------------- 1: init ----------------
__global__ void k_init(const int* __restrict__ labels) {
    int i = blockIdx.x * blockDim.x + threadIdx.x;
    if (i == 0) { g_loss = 0.f; g_lsum = 0; }
    int v = 0;
    if (i < NN) { g_deg[i] = 0; v = labels[i]; }
    #pragma unroll
    for (int off = 16; off; off >>= 1) v += __shfl_down_sync(0xffffffffu, v, off);
    if ((threadIdx.x & 31) == 0 && v) atomicAdd(&g_lsum, v);
}

// ---------------- 2: histogram destinations ----------------
__global__ void k_count(const int* __restrict__ ei) {
    int e = blockIdx.x * blockDim.x + threadIdx.x;
    if (e < NE) {
        unsigned c = (unsigned)ei[NE + e];
        if (c < NN) atomicAdd(&g_deg[c], 1);
    }
}

// ---------------- 3: 1-block scan -> rowstart, cursor, dinv ----------------
__global__ void k_scan() {
    const int T = 1024;
    const int CH = (NN + T - 1) / T;
    __shared__ int sh[T];
    int tid = threadIdx.x;
    int lo = tid * CH, hi = lo + CH; if (hi > NN) hi = NN;
    int s = 0;
    for (int i = lo; i < hi; i++) s += g_deg[i];
    sh[tid] = s;
    __syncthreads();
    for (int off = 1; off < T; off <<= 1) {
        int v = (tid >= off) ? sh[tid - off] : 0;
        __syncthreads();
        sh[tid] += v;
        __syncthreads();
    }
    int run = sh[tid] - s;
    for (int i = lo; i < hi; i++) {
        int d = g_deg[i];
        g_rowstart[i] = run;
        g_cursor[i]   = run;
        g_dinv[i]     = rsqrtf((float)(d + 1));
        run += d;
    }
    if (tid == T - 1) g_rowstart[NN] = run;
}

// ---------------- GEMM: t[i,:] = (hin[i,:] @ W) * dinv[i] ----------------
// block 256 = 64 cols x 4 row-threads (8 rows each); tile = 32 rows.
// Same fmaf accumulation order as the proven R4 kernel; h rows read directly
// from gmem (__ldg float4, warp-uniform address -> broadcast) instead of smem.
template <int K, bool USEG>
__global__ void __launch_bounds__(256, 6) k_gemm(const float* __restrict__ hin,
                                                 const float* __restrict__ W) {
    __shared__ __align__(16) float sW[K * HD];   // K=128: 32KB, K=64: 16KB
    const float* src = USEG ? g_h : hin;
    int tid = threadIdx.x;
    for (int j = tid; j < K * HD / 4; j += 256)
        ((float4*)sW)[j] = ((const float4*)W)[j];
    __syncthreads();

    int c  = tid & 63;     // column 0..63
    int rt = tid >> 6;     // row-thread 0..3, owns rows rt*8..rt*8+7
    int rb = blockIdx.x * 32;   // NN % 32 == 0, one tile per block

    const float4* __restrict__ row[8];
    #pragma unroll
    for (int rr = 0; rr < 8; rr++)
        row[rr] = (const float4*)(src + (size_t)(rb + rt * 8 + rr) * K);

    float acc[8];
    #pragma unroll
    for (int rr = 0; rr < 8; rr++) acc[rr] = 0.f;

    #pragma unroll
    for (int k4 = 0; k4 < K / 4; k4++) {
        float w0 = sW[(4 * k4 + 0) * HD + c];
        float w1 = sW[(4 * k4 + 1) * HD + c];
        float w2 = sW[(4 * k4 + 2) * HD + c];
        float w3 = sW[(4 * k4 + 3) * HD + c];
        #pragma unroll
        for (int rr = 0; rr < 8; rr++) {
            float4 h = __ldg(&row[rr][k4]);
            acc[rr] = fmaf(h.x, w0, acc[rr]);
            acc[rr] = fmaf(h.y, w1, acc[rr]);
            acc[rr] = fmaf(h.z, w2, acc[rr]);
            acc[rr] = fmaf(h.w, w3, acc[rr]);
        }
    }
    #pragma unroll
    for (int rr = 0; rr < 8; rr++) {
        int gr = rb + rt * 8 + rr;
        g_t[(size_t)gr * HD + c] = acc[rr] * g_dinv[gr];
    }
}

// ---------------- fill CSR ----------------
__global__ void k_fill(const int* __restrict__ ei) {
    int e = blockIdx.x * blockDim.x + threadIdx.x;
    if (e >= NE) return;
    unsigned src = (unsigned)ei[e];
    unsigned dst = (unsigned)ei[NE + e];
    if (src >= NN || dst >= NN) return;
    int pos = atomicAdd(&g_cursor[dst], 1);
    g_csr[pos] = (int)src;
}

// ---------------- agg + combine: h = relu(dinv[c]*(t[c]+sum t[src]) + b) ----
__global__ void k_agg(const float* __restrict__ b) {
    int tid  = threadIdx.x;
    int node = blockIdx.x * 16 + (tid >> 4);   // NN % 16 == 0
    int part = tid & 15;

    const float4* __restrict__ t4 = (const float4*)g_t;
    int s = g_rowstart[node];
    int e = g_rowstart[node + 1];

    float4 acc = t4[(size_t)node * 16 + part];   // self loop
    int i = s;
    for (; i + 4 <= e; i += 4) {
        int s0 = g_csr[i], s1 = g_csr[i + 1], s2 = g_csr[i + 2], s3 = g_csr[i + 3];
        float4 v0 = t4[(size_t)s0 * 16 + part];
        float4 v1 = t4[(size_t)s1 * 16 + part];
        float4 v2 = t4[(size_t)s2 * 16 + part];
        float4 v3 = t4[(size_t)s3 * 16 + part];
        acc.x += v0.x + v1.x + v2.x + v3.x;
        acc.y += v0.y + v1.y + v2.y + v3.y;
        acc.z += v0.z + v1.z + v2.z + v3.z;
        acc.w += v0.w + v1.w + v2.w + v3.w;
    }
    for (; i < e; i++) {
        float4 v = t4[(size_t)g_csr[i] * 16 + part];
        acc.x += v.x; acc.y += v.y; acc.z += v.z; acc.w += v.w;
    }

    float d = g_dinv[node];
    float4 bb = *(const float4*)&b[part * 4];
    float4 o;
    o.x = fmaxf(fmaf(d, acc.x, bb.x), 0.f);
    o.y = fmaxf(fmaf(d, acc.y, bb.y), 0.f);
    o.z = fmaxf(fmaf(d, acc.z, bb.z), 0.f);
    o.w = fmaxf(fmaf(d, acc.w, bb.w), 0.f);
    ((float4*)g_h)[(size_t)node * 16 + part] = o;
}

// ---------------- MLP head + p output + weighted-BCE ----------------
__global__ void k_head(const float* __restrict__ lW1, const float* __restrict__ lb1,
                       const float* __restrict__ lW2, const float* __restrict__ lb2,
                       const int* __restrict__ labels, float* __restrict__ out_p) {
    __shared__ float sW1[HD * 8];
    __shared__ float sb1[8];
    __shared__ float sW2[8];
    __shared__ float swsum[8];
    int tid = threadIdx.x;
    for (int j = tid; j < HD * 8; j += 256) sW1[j] = lW1[j];
    if (tid < 8) { sb1[tid] = lb1[tid]; sW2[tid] = lW2[tid]; }
    __syncthreads();

    int i = blockIdx.x * 256 + tid;
    float term = 0.f;
    if (i < NN) {
        float z[8];
        #pragma unroll
        for (int o = 0; o < 8; o++) z[o] = sb1[o];
        const float* hr = &g_h[(size_t)i * HD];
        #pragma unroll
        for (int j4 = 0; j4 < HD; j4 += 4) {
            float4 hv = *(const float4*)&hr[j4];
            #pragma unroll
            for (int o = 0; o < 8; o++) {
                z[o] = fmaf(hv.x, sW1[(j4 + 0) * 8 + o], z[o]);
                z[o] = fmaf(hv.y, sW1[(j4 + 1) * 8 + o], z[o]);
                z[o] = fmaf(hv.z, sW1[(j4 + 2) * 8 + o], z[o]);
                z[o] = fmaf(hv.w, sW1[(j4 + 3) * 8 + o], z[o]);
            }
        }
        float z2 = lb2[0];
        #pragma unroll
        for (int o = 0; o < 8; o++) z2 += fmaxf(z[o], 0.f) * sW2[o];
        float p = 1.f / (1.f + expf(-z2));
        out_p[i] = p;

        float pm = (float)g_lsum * (1.0f / NN);
        float y = (float)labels[i];
        float w = y * (1.f - pm) + (1.f - y) * pm;
        float pc = fminf(fmaxf(p, 1e-7f), 1.f - 1e-7f);
        float bce = -(y * logf(pc) + (1.f - y) * logf(1.f - pc));
        term = w * bce;
    }
    #pragma unroll
    for (int off = 16; off; off >>= 1) term += __shfl_down_sync(0xffffffffu, term, off);
    if ((tid & 31) == 0) swsum[tid >> 5] = term;
    __syncthreads();
    if (tid == 0) {
        float s = 0.f;
        #pragma unroll
        for (int k2 = 0; k2 < 8; k2++) s += swsum[k2];
        atomicAdd(&g_loss, s);
    }
}

__global__ void k_final(float* __restrict__ out) {
    out[0] = g_loss * (1.0f / NN);
}

// ---------------- launch ----------------
extern "C" void kernel_launch(void* const* d_in, const int* in_sizes, int n_in,
                              void* d_out, int out_size) {
    const float* x      = (const float*)d_in[0];
    const int*   ei     = (const int*)d_in[1];
    const int*   labels = (const int*)d_in[2];
    const float* W1  = (const float*)d_in[3];
    const float* b1  = (const float*)d_in[4];
    const float* W2  = (const float*)d_in[5];
    const float* b2  = (const float*)d_in[6];
    const float* W3  = (const float*)d_in[7];
    const float* b3  = (const float*)d_in[8];
    const float* lW1 = (const float*)d_in[9];
    const float* lb1 = (const float*)d_in[10];
    const float* lW2 = (const float*)d_in[11];
    const float* lb2 = (const float*)d_in[12];

    float* out = (float*)d_out;
    int loss_elems = out_size - NN;
    float* out_p = out + (loss_elems > 0 ? loss_elems : 0);

    const int TPB = 256;
    const int NB_N = (NN + TPB - 1) / TPB;
    const int NB_E = (NE + TPB - 1) / TPB;
    const int agg_blocks  = NN / 16;   // 6250
    const int gemm_blocks = NN / 32;   // 3125

    k_init <<<NB_N, TPB>>>(labels);                         // 1
    k_count<<<NB_E, TPB>>>(ei);                             // 2
    k_scan <<<1, 1024>>>();                                 // 3 (dinv ready)
    k_gemm<NF, false><<<gemm_blocks, TPB>>>(x, W1);         // 4  <- profiled
    k_fill <<<NB_E, TPB>>>(ei);                             // 5
    k_agg<<<agg_blocks, TPB>>>(b1);                         // 6

    k_gemm<HD, true><<<gemm_blocks, TPB>>>(nullptr, W2);    // 7
    k_agg<<<agg_blocks, TPB>>>(b2);                         // 8

    k_gemm<HD, true><<<gemm_blocks, TPB>>>(nullptr, W3);    // 9
    k_agg<<<agg_blocks, TPB>>>(b3);                         // 10

    k_head<<<NB_N, TPB>>>(lW1, lb1, lW2, lb2, labels, out_p);  // 11
    if (loss_elems > 0) k_final<<<1, 1>>>(out);             // 12
}

// round 8
// speedup vs baseline: 1.4005x; 1.4005x over previous
#include <cuda_runtime.h>
#include <cstdint>

#define NN 100000
#define NE 1600000
#define NF 128
#define HD 64

#define GEMM1_BLOCKS 592
#define COUNT_BLOCKS ((NE + 255) / 256)   // 6250
#define FILL_BLOCKS  ((NE + 255) / 256)   // 6250
#define TS_BLOCKS    (NN * HD / 4 / 256)  // 6250

// ---------------- scratch (no allocs allowed) ----------------
__device__ __align__(16) float g_dinv[NN];
__device__ __align__(16) float g_t  [NN * HD];   // (h @ W) [* dinv[row]]
__device__ __align__(16) float g_h  [NN * HD];   // layer output
__device__ int g_deg[NN];
__device__ int g_cursor[NN];
__device__ int g_rowstart[NN + 1];
__device__ int g_csr[NE];
__device__ float g_loss;
__device__ int   g_lsum;

// ---------------- 1: init ----------------
__global__ void k_init(const int* __restrict__ labels) {
    int i = blockIdx.x * blockDim.x + threadIdx.x;
    if (i == 0) { g_loss = 0.f; g_lsum = 0; }
    int v = 0;
    if (i < NN) { g_deg[i] = 0; v = labels[i]; }
    #pragma unroll
    for (int off = 16; off; off >>= 1) v += __shfl_down_sync(0xffffffffu, v, off);
    if ((threadIdx.x & 31) == 0 && v) atomicAdd(&g_lsum, v);
}

// ---------------- gemm inner body (proven R4 version) ----------------
template <int K, bool USEG, bool PRESCALE>
__device__ __forceinline__ void gemm_body(const float* __restrict__ hin,
                                          const float* __restrict__ W,
                                          float* sW, float4 (*srow)[32],
                                          int bid, int nblocks) {
    const float* src = USEG ? g_h : hin;
    int tid = threadIdx.x;
    for (int j = tid; j < K * HD / 4; j += 256)
        ((float4*)sW)[j] = ((const float4*)W)[j];

    int c  = tid & 63;     // column 0..63
    int rt = tid >> 6;     // row-thread 0..3, owns rows rt*8..rt*8+7

    for (int rb = bid * 32; rb < NN; rb += nblocks * 32) {
        __syncthreads();
        for (int j = tid; j < 32 * (K / 4); j += 256) {
            int r = j / (K / 4), kk = j % (K / 4);
            srow[kk][r] = ((const float4*)(src + (size_t)(rb + r) * K))[kk];
        }
        __syncthreads();

        float acc[8];
        #pragma unroll
        for (int rr = 0; rr < 8; rr++) acc[rr] = 0.f;

        #pragma unroll
        for (int k4 = 0; k4 < K / 4; k4++) {
            float w0 = sW[(4 * k4 + 0) * HD + c];
            float w1 = sW[(4 * k4 + 1) * HD + c];
            float w2 = sW[(4 * k4 + 2) * HD + c];
            float w3 = sW[(4 * k4 + 3) * HD + c];
            #pragma unroll
            for (int rr = 0; rr < 8; rr++) {
                float4 h = srow[k4][rt * 8 + rr];
                acc[rr] = fmaf(h.x, w0, acc[rr]);
                acc[rr] = fmaf(h.y, w1, acc[rr]);
                acc[rr] = fmaf(h.z, w2, acc[rr]);
                acc[rr] = fmaf(h.w, w3, acc[rr]);
            }
        }
        #pragma unroll
        for (int rr = 0; rr < 8; rr++) {
            int gr = rb + rt * 8 + rr;
            g_t[(size_t)gr * HD + c] = PRESCALE ? acc[rr] * g_dinv[gr] : acc[rr];
        }
    }
}

// ---------------- 2: fused [gemm1 (no prescale) || count] ----------------
__global__ void __launch_bounds__(256) k_gemm1_count(const float* __restrict__ x,
                                                     const float* __restrict__ W1,
                                                     const int* __restrict__ ei) {
    __shared__ __align__(16) float  sW[NF * HD];      // 32KB
    __shared__ __align__(16) float4 srow[NF / 4][32]; // 16KB
    int bid = blockIdx.x;
    if (bid < GEMM1_BLOCKS) {
        gemm_body<NF, false, false>(x, W1, sW, srow, bid, GEMM1_BLOCKS);
    } else {
        int e = (bid - GEMM1_BLOCKS) * 256 + threadIdx.x;
        if (e < NE) {
            unsigned c = (unsigned)ei[NE + e];
            if (c < NN) atomicAdd(&g_deg[c], 1);
        }
    }
}

// ---------------- 3: 1-block scan -> rowstart, cursor, dinv ----------------
__global__ void k_scan() {
    const int T = 1024;
    const int CH = (NN + T - 1) / T;
    __shared__ int sh[T];
    int tid = threadIdx.x;
    int lo = tid * CH, hi = lo + CH; if (hi > NN) hi = NN;
    int s = 0;
    for (int i = lo; i < hi; i++) s += g_deg[i];
    sh[tid] = s;
    __syncthreads();
    for (int off = 1; off < T; off <<= 1) {
        int v = (tid >= off) ? sh[tid - off] : 0;
        __syncthreads();
        sh[tid] += v;
        __syncthreads();
    }
    int run = sh[tid] - s;
    for (int i = lo; i < hi; i++) {
        int d = g_deg[i];
        g_rowstart[i] = run;
        g_cursor[i]   = run;
        g_dinv[i]     = rsqrtf((float)(d + 1));
        run += d;
    }
    if (tid == T - 1) g_rowstart[NN] = run;
}

// ---------------- 4: fused [fill || t *= dinv[row]] ----------------
__global__ void k_fill_tscale(const int* __restrict__ ei) {
    int bid = blockIdx.x;
    if (bid < FILL_BLOCKS) {
        int e = bid * 256 + threadIdx.x;
        if (e < NE) {
            unsigned src = (unsigned)ei[e];
            unsigned dst = (unsigned)ei[NE + e];
            if (src < NN && dst < NN) {
                int pos = atomicAdd(&g_cursor[dst], 1);
                g_csr[pos] = (int)src;
            }
        }
    } else {
        int idx = (bid - FILL_BLOCKS) * 256 + threadIdx.x;  // float4 units
        int node = idx >> 4;
        float d = g_dinv[node];
        float4 v = ((const float4*)g_t)[idx];
        v.x *= d; v.y *= d; v.z *= d; v.w *= d;
        ((float4*)g_t)[idx] = v;
    }
}

// ---------------- gemm2/3 standalone (prescale) ----------------
template <int K, bool USEG, bool PRESCALE>
__global__ void __launch_bounds__(256) k_gemm(const float* __restrict__ hin,
                                              const float* __restrict__ W) {
    __shared__ __align__(16) float  sW[K * HD];
    __shared__ __align__(16) float4 srow[K / 4][32];
    gemm_body<K, USEG, PRESCALE>(hin, W, sW, srow, blockIdx.x, gridDim.x);
}

// ---------------- agg + combine: h = relu(dinv[c]*(t[c]+sum t[src]) + b) ----
// 16 threads per node (each owns one float4 of the 64-wide row); unroll 2
__global__ void k_agg(const float* __restrict__ b) {
    int tid  = threadIdx.x;
    int node = blockIdx.x * 16 + (tid >> 4);   // NN % 16 == 0
    int part = tid & 15;

    const float4* __restrict__ t4 = (const float4*)g_t;
    int s = g_rowstart[node];
    int e = g_rowstart[node + 1];

    float4 acc = t4[(size_t)node * 16 + part];   // self loop
    int i = s;
    for (; i + 2 <= e; i += 2) {
        int s0 = g_csr[i];
        int s1 = g_csr[i + 1];
        float4 v0 = t4[(size_t)s0 * 16 + part];
        float4 v1 = t4[(size_t)s1 * 16 + part];
        acc.x += v0.x; acc.y += v0.y; acc.z += v0.z; acc.w += v0.w;
        acc.x += v1.x; acc.y += v1.y; acc.z += v1.z; acc.w += v1.w;
    }
    if (i < e) {
        float4 v = t4[(size_t)g_csr[i] * 16 + part];
        acc.x += v.x; acc.y += v.y; acc.z += v.z; acc.w += v.w;
    }

    float d = g_dinv[node];
    float4 bb = *(const float4*)&b[part * 4];
    float4 o;
    o.x = fmaxf(fmaf(d, acc.x, bb.x), 0.f);
    o.y = fmaxf(fmaf(d, acc.y, bb.y), 0.f);
    o.z = fmaxf(fmaf(d, acc.z, bb.z), 0.f);
    o.w = fmaxf(fmaf(d, acc.w, bb.w), 0.f);
    ((float4*)g_h)[(size_t)node * 16 + part] = o;
}

// ---------------- MLP head + p output + weighted-BCE ----------------
__global__ void k_head(const float* __restrict__ lW1, const float* __restrict__ lb1,
                       const float* __restrict__ lW2, const float* __restrict__ lb2,
                       const int* __restrict__ labels, float* __restrict__ out_p) {
    __shared__ float sW1[HD * 8];
    __shared__ float sb1[8];
    __shared__ float sW2[8];
    __shared__ float swsum[8];
    int tid = threadIdx.x;
    for (int j = tid; j < HD * 8; j += 256) sW1[j] = lW1[j];
    if (tid < 8) { sb1[tid] = lb1[tid]; sW2[tid] = lW2[tid]; }
    __syncthreads();

    int i = blockIdx.x * 256 + tid;
    float term = 0.f;
    if (i < NN) {
        float z[8];
        #pragma unroll
        for (int o = 0; o < 8; o++) z[o] = sb1[o];
        const float* hr = &g_h[(size_t)i * HD];
        #pragma unroll
        for (int j4 = 0; j4 < HD; j4 += 4) {
            float4 hv = *(const float4*)&hr[j4];
            #pragma unroll
            for (int o = 0; o < 8; o++) {
                z[o] = fmaf(hv.x, sW1[(j4 + 0) * 8 + o], z[o]);
                z[o] = fmaf(hv.y, sW1[(j4 + 1) * 8 + o], z[o]);
                z[o] = fmaf(hv.z, sW1[(j4 + 2) * 8 + o], z[o]);
                z[o] = fmaf(hv.w, sW1[(j4 + 3) * 8 + o], z[o]);
            }
        }
        float z2 = lb2[0];
        #pragma unroll
        for (int o = 0; o < 8; o++) z2 += fmaxf(z[o], 0.f) * sW2[o];
        float p = 1.f / (1.f + expf(-z2));
        out_p[i] = p;

        float pm = (float)g_lsum * (1.0f / NN);
        float y = (float)labels[i];
        float w = y * (1.f - pm) + (1.f - y) * pm;
        float pc = fminf(fmaxf(p, 1e-7f), 1.f - 1e-7f);
        float bce = -(y * logf(pc) + (1.f - y) * logf(1.f - pc));
        term = w * bce;
    }
    #pragma unroll
    for (int off = 16; off; off >>= 1) term += __shfl_down_sync(0xffffffffu, term, off);
    if ((tid & 31) == 0) swsum[tid >> 5] = term;
    __syncthreads();
    if (tid == 0) {
        float s = 0.f;
        #pragma unroll
        for (int k2 = 0; k2 < 8; k2++) s += swsum[k2];
        atomicAdd(&g_loss, s);
    }
}

__global__ void k_final(float* __restrict__ out) {
    out[0] = g_loss * (1.0f / NN);
}

// ---------------- launch ----------------
extern "C" void kernel_launch(void* const* d_in, const int* in_sizes, int n_in,
                              void* d_out, int out_size) {
    const float* x      = (const float*)d_in[0];
    const int*   ei     = (const int*)d_in[1];
    const int*   labels = (const int*)d_in[2];
    const float* W1  = (const float*)d_in[3];
    const float* b1  = (const float*)d_in[4];
    const float* W2  = (const float*)d_in[5];
    const float* b2  = (const float*)d_in[6];
    const float* W3  = (const float*)d_in[7];
    const float* b3  = (const float*)d_in[8];
    const float* lW1 = (const float*)d_in[9];
    const float* lb1 = (const float*)d_in[10];
    const float* lW2 = (const float*)d_in[11];
    const float* lb2 = (const float*)d_in[12];

    float* out = (float*)d_out;
    int loss_elems = out_size - NN;
    float* out_p = out + (loss_elems > 0 ? loss_elems : 0);

    const int TPB = 256;
    const int NB_N = (NN + TPB - 1) / TPB;
    const int agg_blocks = NN / 16;   // 6250

    k_init <<<NB_N, TPB>>>(labels);                                     // 1
    k_gemm1_count<<<GEMM1_BLOCKS + COUNT_BLOCKS, TPB>>>(x, W1, ei);     // 2
    k_scan <<<1, 1024>>>();                                             // 3
    k_fill_tscale<<<FILL_BLOCKS + TS_BLOCKS, TPB>>>(ei);                // 4 <- profiled
    k_agg<<<agg_blocks, TPB>>>(b1);                                     // 5

    k_gemm<HD, true, true><<<GEMM1_BLOCKS, TPB>>>(nullptr, W2);         // 6
    k_agg<<<agg_blocks, TPB>>>(b2);                                     // 7

    k_gemm<HD, true, true><<<GEMM1_BLOCKS, TPB>>>(nullptr, W3);         // 8
    k_agg<<<agg_blocks, TPB>>>(b3);                                     // 9

    k_head<<<NB_N, TPB>>>(lW1, lb1, lW2, lb2, labels, out_p);           // 10
    if (loss_elems > 0) k_final<<<1, 1>>>(out);                         // 11
}

// round 9
// speedup vs baseline: 1.4060x; 1.0039x over previous
#include <cuda_runtime.h>
#include <cstdint>

#define NN 100000
#define NE 1600000
#define NF 128
#define HD 64

// ---------------- scratch (no allocs allowed) ----------------
__device__ __align__(16) float g_dinv[NN];
__device__ __align__(16) float g_t  [NN * HD];   // (h @ W) * dinv[row]
__device__ __align__(16) float g_h  [NN * HD];   // layer output
__device__ int g_deg[NN];
__device__ int g_cursor[NN];
__device__ int g_rowstart[NN + 1];
__device__ int g_csr[NE];
__device__ float g_loss;
__device__ int   g_lsum;

// ---------------- 1: init ----------------
__global__ void k_init(const int* __restrict__ labels) {
    int i = blockIdx.x * blockDim.x + threadIdx.x;
    if (i == 0) { g_loss = 0.f; g_lsum = 0; }
    int v = 0;
    if (i < NN) { g_deg[i] = 0; v = labels[i]; }
    #pragma unroll
    for (int off = 16; off; off >>= 1) v += __shfl_down_sync(0xffffffffu, v, off);
    if ((threadIdx.x & 31) == 0 && v) atomicAdd(&g_lsum, v);
}

// ---------------- 2: histogram destinations ----------------
__global__ void k_count(const int* __restrict__ ei) {
    int e = blockIdx.x * blockDim.x + threadIdx.x;
    if (e < NE) {
        unsigned c = (unsigned)ei[NE + e];
        if (c < NN) atomicAdd(&g_deg[c], 1);
    }
}

// ---------------- 3: 1-block scan -> rowstart, cursor, dinv ----------------
__global__ void k_scan() {
    const int T = 1024;
    const int CH = (NN + T - 1) / T;
    __shared__ int sh[T];
    int tid = threadIdx.x;
    int lo = tid * CH, hi = lo + CH; if (hi > NN) hi = NN;
    int s = 0;
    for (int i = lo; i < hi; i++) s += g_deg[i];
    sh[tid] = s;
    __syncthreads();
    for (int off = 1; off < T; off <<= 1) {
        int v = (tid >= off) ? sh[tid - off] : 0;
        __syncthreads();
        sh[tid] += v;
        __syncthreads();
    }
    int run = sh[tid] - s;
    for (int i = lo; i < hi; i++) {
        int d = g_deg[i];
        g_rowstart[i] = run;
        g_cursor[i]   = run;
        g_dinv[i]     = rsqrtf((float)(d + 1));
        run += d;
    }
    if (tid == T - 1) g_rowstart[NN] = run;
}

// ---------------- GEMM: t[i,:] = (hin[i,:] @ W) * dinv[i] ----------------
// block 256 = 64 cols x 4 k-quarter threads; tile = 8 rows.
// W column-slice lives in registers (loaded once per block, coalesced).
// Each thread accumulates its k-quarter for 8 rows; quarters reduced via smem.
template <int K, bool USEG>
__global__ void __launch_bounds__(256) k_gemm(const float* __restrict__ hin,
                                              const float* __restrict__ W) {
    constexpr int KQ  = K / 4;    // k's per quarter
    constexpr int NK4 = K / 4;    // float4 per row
    constexpr int QK4 = K / 16;   // float4 per quarter
    __shared__ __align__(16) float4 srow[8][NK4];   // [row][k4]
    __shared__ float spart[4][8][HD];               // 8KB
    const float* src = USEG ? g_h : hin;

    int tid = threadIdx.x;
    int c   = tid & 63;    // column
    int kt  = tid >> 6;    // k-quarter 0..3

    float wreg[KQ];
    #pragma unroll
    for (int j = 0; j < KQ; j++)
        wreg[j] = __ldg(&W[(kt * KQ + j) * HD + c]);   // coalesced across c

    for (int rb = blockIdx.x * 8; rb < NN; rb += gridDim.x * 8) {
        // stage 8 rows
        #pragma unroll
        for (int j = tid; j < 8 * NK4; j += 256) {
            int r  = j / NK4;
            int k4 = j % NK4;
            srow[r][k4] = ((const float4*)(src + (size_t)(rb + r) * K))[k4];
        }
        __syncthreads();

        float acc[8];
        #pragma unroll
        for (int r = 0; r < 8; r++) acc[r] = 0.f;

        #pragma unroll
        for (int j4 = 0; j4 < QK4; j4++) {
            float w0 = wreg[4 * j4 + 0];
            float w1 = wreg[4 * j4 + 1];
            float w2 = wreg[4 * j4 + 2];
            float w3 = wreg[4 * j4 + 3];
            #pragma unroll
            for (int r = 0; r < 8; r++) {
                float4 h = srow[r][kt * QK4 + j4];   // warp-broadcast LDS.128
                acc[r] = fmaf(h.x, w0, acc[r]);
                acc[r] = fmaf(h.y, w1, acc[r]);
                acc[r] = fmaf(h.z, w2, acc[r]);
                acc[r] = fmaf(h.w, w3, acc[r]);
            }
        }

        // write partials (no sync needed: spart readers finished before the
        // post-load __syncthreads above)
        #pragma unroll
        for (int r = 0; r < 8; r++) spart[kt][r][c] = acc[r];
        __syncthreads();

        // reduce quarters: 512 outputs, 2 per thread
        #pragma unroll
        for (int p = 0; p < 2; p++) {
            int idx = tid + p * 256;
            int r   = idx >> 6;
            int cc  = idx & 63;
            float v = ((spart[0][r][cc] + spart[1][r][cc]) + spart[2][r][cc]) + spart[3][r][cc];
            int gr = rb + r;
            g_t[(size_t)gr * HD + cc] = v * g_dinv[gr];
        }
        __syncthreads();
    }
}

// ---------------- fill CSR ----------------
__global__ void k_fill(const int* __restrict__ ei) {
    int e = blockIdx.x * blockDim.x + threadIdx.x;
    if (e >= NE) return;
    unsigned src = (unsigned)ei[e];
    unsigned dst = (unsigned)ei[NE + e];
    if (src >= NN || dst >= NN) return;
    int pos = atomicAdd(&g_cursor[dst], 1);
    g_csr[pos] = (int)src;
}

// ---------------- agg + combine: h = relu(dinv[c]*(t[c]+sum t[src]) + b) ----
// 16 threads per node (each owns one float4 of the 64-wide row); unroll 2
__global__ void k_agg(const float* __restrict__ b) {
    int tid  = threadIdx.x;
    int node = blockIdx.x * 16 + (tid >> 4);   // NN % 16 == 0
    int part = tid & 15;

    const float4* __restrict__ t4 = (const float4*)g_t;
    int s = g_rowstart[node];
    int e = g_rowstart[node + 1];

    float4 acc = t4[(size_t)node * 16 + part];   // self loop
    int i = s;
    for (; i + 2 <= e; i += 2) {
        int s0 = g_csr[i];
        int s1 = g_csr[i + 1];
        float4 v0 = t4[(size_t)s0 * 16 + part];
        float4 v1 = t4[(size_t)s1 * 16 + part];
        acc.x += v0.x; acc.y += v0.y; acc.z += v0.z; acc.w += v0.w;
        acc.x += v1.x; acc.y += v1.y; acc.z += v1.z; acc.w += v1.w;
    }
    if (i < e) {
        float4 v = t4[(size_t)g_csr[i] * 16 + part];
        acc.x += v.x; acc.y += v.y; acc.z += v.z; acc.w += v.w;
    }

    float d = g_dinv[node];
    float4 bb = *(const float4*)&b[part * 4];
    float4 o;
    o.x = fmaxf(fmaf(d, acc.x, bb.x), 0.f);
    o.y = fmaxf(fmaf(d, acc.y, bb.y), 0.f);
    o.z = fmaxf(fmaf(d, acc.z, bb.z), 0.f);
    o.w = fmaxf(fmaf(d, acc.w, bb.w), 0.f);
    ((float4*)g_h)[(size_t)node * 16 + part] = o;
}

// ---------------- MLP head + p output + weighted-BCE ----------------
__global__ void k_head(const float* __restrict__ lW1, const float* __restrict__ lb1,
                       const float* __restrict__ lW2, const float* __restrict__ lb2,
                       const int* __restrict__ labels, float* __restrict__ out_p) {
    __shared__ float sW1[HD * 8];
    __shared__ float sb1[8];
    __shared__ float sW2[8];
    __shared__ float swsum[8];
    int tid = threadIdx.x;
    for (int j = tid; j < HD * 8; j += 256) sW1[j] = lW1[j];
    if (tid < 8) { sb1[tid] = lb1[tid]; sW2[tid] = lW2[tid]; }
    __syncthreads();

    int i = blockIdx.x * 256 + tid;
    float term = 0.f;
    if (i < NN) {
        float z[8];
        #pragma unroll
        for (int o = 0; o < 8; o++) z[o] = sb1[o];
        const float* hr = &g_h[(size_t)i * HD];
        #pragma unroll
        for (int j4 = 0; j4 < HD; j4 += 4) {
            float4 hv = *(const float4*)&hr[j4];
            #pragma unroll
            for (int o = 0; o < 8; o++) {
                z[o] = fmaf(hv.x, sW1[(j4 + 0) * 8 + o], z[o]);
                z[o] = fmaf(hv.y, sW1[(j4 + 1) * 8 + o], z[o]);
                z[o] = fmaf(hv.z, sW1[(j4 + 2) * 8 + o], z[o]);
                z[o] = fmaf(hv.w, sW1[(j4 + 3) * 8 + o], z[o]);
            }
        }
        float z2 = lb2[0];
        #pragma unroll
        for (int o = 0; o < 8; o++) z2 += fmaxf(z[o], 0.f) * sW2[o];
        float p = 1.f / (1.f + expf(-z2));
        out_p[i] = p;

        float pm = (float)g_lsum * (1.0f / NN);
        float y = (float)labels[i];
        float w = y * (1.f - pm) + (1.f - y) * pm;
        float pc = fminf(fmaxf(p, 1e-7f), 1.f - 1e-7f);
        float bce = -(y * logf(pc) + (1.f - y) * logf(1.f - pc));
        term = w * bce;
    }
    #pragma unroll
    for (int off = 16; off; off >>= 1) term += __shfl_down_sync(0xffffffffu, term, off);
    if ((tid & 31) == 0) swsum[tid >> 5] = term;
    __syncthreads();
    if (tid == 0) {
        float s = 0.f;
        #pragma unroll
        for (int k2 = 0; k2 < 8; k2++) s += swsum[k2];
        atomicAdd(&g_loss, s);
    }
}

__global__ void k_final(float* __restrict__ out) {
    out[0] = g_loss * (1.0f / NN);
}

// ---------------- launch ----------------
extern "C" void kernel_launch(void* const* d_in, const int* in_sizes, int n_in,
                              void* d_out, int out_size) {
    const float* x      = (const float*)d_in[0];
    const int*   ei     = (const int*)d_in[1];
    const int*   labels = (const int*)d_in[2];
    const float* W1  = (const float*)d_in[3];
    const float* b1  = (const float*)d_in[4];
    const float* W2  = (const float*)d_in[5];
    const float* b2  = (const float*)d_in[6];
    const float* W3  = (const float*)d_in[7];
    const float* b3  = (const float*)d_in[8];
    const float* lW1 = (const float*)d_in[9];
    const float* lb1 = (const float*)d_in[10];
    const float* lW2 = (const float*)d_in[11];
    const float* lb2 = (const float*)d_in[12];

    float* out = (float*)d_out;
    int loss_elems = out_size - NN;
    float* out_p = out + (loss_elems > 0 ? loss_elems : 0);

    const int TPB = 256;
    const int NB_N = (NN + TPB - 1) / TPB;
    const int NB_E = (NE + TPB - 1) / TPB;
    const int agg_blocks  = NN / 16;   // 6250
    const int gemm_blocks = 592;

    k_init <<<NB_N, TPB>>>(labels);                         // 1
    k_count<<<NB_E, TPB>>>(ei);                             // 2
    k_scan <<<1, 1024>>>();                                 // 3 (dinv ready)
    k_gemm<NF, false><<<gemm_blocks, TPB>>>(x, W1);         // 4  <- profiled
    k_fill <<<NB_E, TPB>>>(ei);                             // 5
    k_agg<<<agg_blocks, TPB>>>(b1);                         // 6

    k_gemm<HD, true><<<gemm_blocks, TPB>>>(nullptr, W2);    // 7
    k_agg<<<agg_blocks, TPB>>>(b2);                         // 8

    k_gemm<HD, true><<<gemm_blocks, TPB>>>(nullptr, W3);    // 9
    k_agg<<<agg_blocks, TPB>>>(b3);                         // 10

    k_head<<<NB_N, TPB>>>(lW1, lb1, lW2, lb2, labels, out_p);  // 11
    if (loss_elems > 0) k_final<<<1, 1>>>(out);             // 12
}

// round 10
// speedup vs baseline: 1.4717x; 1.0467x over previous
#include <cuda_runtime.h>
#include <cstdint>

#define NN 100000
#define NE 1600000
#define NF 128
#define HD 64

// ---------------- scratch (no allocs allowed) ----------------
__device__ __align__(16) float g_dinv[NN];
__device__ __align__(16) float g_t  [NN * HD];   // (h @ W) * dinv[row]
__device__ __align__(16) float g_h  [NN * HD];   // layer output
__device__ int g_deg[NN];
__device__ int g_cursor[NN];
__device__ int g_rowstart[NN + 1];
__device__ int g_csr[NE];
__device__ float g_loss;
__device__ int   g_lsum;

// ---------------- 1: init ----------------
__global__ void k_init(const int* __restrict__ labels) {
    int i = blockIdx.x * blockDim.x + threadIdx.x;
    if (i == 0) { g_loss = 0.f; g_lsum = 0; }
    int v = 0;
    if (i < NN) { g_deg[i] = 0; v = labels[i]; }
    #pragma unroll
    for (int off = 16; off; off >>= 1) v += __shfl_down_sync(0xffffffffu, v, off);
    if ((threadIdx.x & 31) == 0 && v) atomicAdd(&g_lsum, v);
}

// ---------------- 2: histogram destinations ----------------
__global__ void k_count(const int* __restrict__ ei) {
    int e = blockIdx.x * blockDim.x + threadIdx.x;
    if (e < NE) {
        unsigned c = (unsigned)ei[NE + e];
        if (c < NN) atomicAdd(&g_deg[c], 1);
    }
}

// ---------------- 3: 1-block scan -> rowstart, cursor, dinv ----------------
__global__ void k_scan() {
    const int T = 1024;
    const int CH = (NN + T - 1) / T;
    __shared__ int sh[T];
    int tid = threadIdx.x;
    int lo = tid * CH, hi = lo + CH; if (hi > NN) hi = NN;
    int s = 0;
    for (int i = lo; i < hi; i++) s += g_deg[i];
    sh[tid] = s;
    __syncthreads();
    for (int off = 1; off < T; off <<= 1) {
        int v = (tid >= off) ? sh[tid - off] : 0;
        __syncthreads();
        sh[tid] += v;
        __syncthreads();
    }
    int run = sh[tid] - s;
    for (int i = lo; i < hi; i++) {
        int d = g_deg[i];
        g_rowstart[i] = run;
        g_cursor[i]   = run;
        g_dinv[i]     = rsqrtf((float)(d + 1));
        run += d;
    }
    if (tid == T - 1) g_rowstart[NN] = run;
}

// ---------------- GEMM: t[i,:] = (hin[i,:] @ W) * dinv[i] ----------------
// block 256 = 32 col-pairs x 8 row-threads (4 rows each); tile = 32 rows.
// Per-element fmaf chain over k is IDENTICAL to the proven R4 kernel.
template <int K, bool USEG>
__global__ void __launch_bounds__(256) k_gemm(const float* __restrict__ hin,
                                              const float* __restrict__ W) {
    __shared__ __align__(16) float  sW[K * HD];        // K=128: 32KB, K=64: 16KB
    __shared__ __align__(16) float4 srow[32][K / 4];   // K=128: 16KB, K=64: 8KB
    const float* src = USEG ? g_h : hin;
    int tid = threadIdx.x;
    for (int j = tid; j < K * HD / 4; j += 256)
        ((float4*)sW)[j] = ((const float4*)W)[j];

    int c2 = tid & 31;    // column pair: cols 2*c2, 2*c2+1
    int rt = tid >> 5;    // row-thread 0..7, owns rows rt*4..rt*4+3

    for (int rb = blockIdx.x * 32; rb < NN; rb += gridDim.x * 32) {
        __syncthreads();
        for (int j = tid; j < 32 * (K / 4); j += 256) {
            int r = j / (K / 4), kk = j % (K / 4);
            srow[r][kk] = ((const float4*)(src + (size_t)(rb + r) * K))[kk];
        }
        __syncthreads();

        float acc0[4], acc1[4];
        #pragma unroll
        for (int rr = 0; rr < 4; rr++) { acc0[rr] = 0.f; acc1[rr] = 0.f; }

        #pragma unroll
        for (int k4 = 0; k4 < K / 4; k4++) {
            float2 wa = *(const float2*)&sW[(4 * k4 + 0) * HD + 2 * c2];
            float2 wb = *(const float2*)&sW[(4 * k4 + 1) * HD + 2 * c2];
            float2 wc = *(const float2*)&sW[(4 * k4 + 2) * HD + 2 * c2];
            float2 wd = *(const float2*)&sW[(4 * k4 + 3) * HD + 2 * c2];
            #pragma unroll
            for (int rr = 0; rr < 4; rr++) {
                float4 h = srow[rt * 4 + rr][k4];   // warp-broadcast LDS.128
                acc0[rr] = fmaf(h.x, wa.x, acc0[rr]);
                acc0[rr] = fmaf(h.y, wb.x, acc0[rr]);
                acc0[rr] = fmaf(h.z, wc.x, acc0[rr]);
                acc0[rr] = fmaf(h.w, wd.x, acc0[rr]);
                acc1[rr] = fmaf(h.x, wa.y, acc1[rr]);
                acc1[rr] = fmaf(h.y, wb.y, acc1[rr]);
                acc1[rr] = fmaf(h.z, wc.y, acc1[rr]);
                acc1[rr] = fmaf(h.w, wd.y, acc1[rr]);
            }
        }
        #pragma unroll
        for (int rr = 0; rr < 4; rr++) {
            int gr = rb + rt * 4 + rr;
            float d = g_dinv[gr];
            float2 o = make_float2(acc0[rr] * d, acc1[rr] * d);
            *(float2*)&g_t[(size_t)gr * HD + 2 * c2] = o;
        }
    }
}

// ---------------- fill CSR ----------------
__global__ void k_fill(const int* __restrict__ ei) {
    int e = blockIdx.x * blockDim.x + threadIdx.x;
    if (e >= NE) return;
    unsigned src = (unsigned)ei[e];
    unsigned dst = (unsigned)ei[NE + e];
    if (src >= NN || dst >= NN) return;
    int pos = atomicAdd(&g_cursor[dst], 1);
    g_csr[pos] = (int)src;
}

// ---- Kahan compensated add (intrinsics resist contraction/reassoc) ----
__device__ __forceinline__ void kadd(float& a, float& c, float v) {
    float y = __fsub_rn(v, c);
    float t = __fadd_rn(a, y);
    c = __fsub_rn(__fsub_rn(t, a), y);
    a = t;
}
__device__ __forceinline__ void kadd4(float4& a, float4& c, float4 v) {
    kadd(a.x, c.x, v.x); kadd(a.y, c.y, v.y);
    kadd(a.z, c.z, v.z); kadd(a.w, c.w, v.w);
}

// ---------------- agg + combine: h = relu(dinv[c]*(t[c]+sum t[src]) + b) ----
// 16 threads per node; Kahan-compensated sum (order-insensitive to ~1e-7)
__global__ void k_agg(const float* __restrict__ b) {
    int tid  = threadIdx.x;
    int node = blockIdx.x * 16 + (tid >> 4);   // NN % 16 == 0
    int part = tid & 15;

    const float4* __restrict__ t4 = (const float4*)g_t;
    int s = g_rowstart[node];
    int e = g_rowstart[node + 1];

    float4 acc  = t4[(size_t)node * 16 + part];   // self loop
    float4 comp = make_float4(0.f, 0.f, 0.f, 0.f);
    int i = s;
    for (; i + 2 <= e; i += 2) {
        int s0 = g_csr[i];
        int s1 = g_csr[i + 1];
        float4 v0 = t4[(size_t)s0 * 16 + part];
        float4 v1 = t4[(size_t)s1 * 16 + part];
        kadd4(acc, comp, v0);
        kadd4(acc, comp, v1);
    }
    if (i < e) {
        float4 v = t4[(size_t)g_csr[i] * 16 + part];
        kadd4(acc, comp, v);
    }

    float d = g_dinv[node];
    float4 bb = *(const float4*)&b[part * 4];
    float4 o;
    o.x = fmaxf(fmaf(d, acc.x, bb.x), 0.f);
    o.y = fmaxf(fmaf(d, acc.y, bb.y), 0.f);
    o.z = fmaxf(fmaf(d, acc.z, bb.z), 0.f);
    o.w = fmaxf(fmaf(d, acc.w, bb.w), 0.f);
    ((float4*)g_h)[(size_t)node * 16 + part] = o;
}

// ---------------- MLP head + p output + weighted-BCE ----------------
__global__ void k_head(const float* __restrict__ lW1, const float* __restrict__ lb1,
                       const float* __restrict__ lW2, const float* __restrict__ lb2,
                       const int* __restrict__ labels, float* __restrict__ out_p) {
    __shared__ float sW1[HD * 8];
    __shared__ float sb1[8];
    __shared__ float sW2[8];
    __shared__ float swsum[8];
    int tid = threadIdx.x;
    for (int j = tid; j < HD * 8; j += 256) sW1[j] = lW1[j];
    if (tid < 8) { sb1[tid] = lb1[tid]; sW2[tid] = lW2[tid]; }
    __syncthreads();

    int i = blockIdx.x * 256 + tid;
    float term = 0.f;
    if (i < NN) {
        float z[8];
        #pragma unroll
        for (int o = 0; o < 8; o++) z[o] = sb1[o];
        const float* hr = &g_h[(size_t)i * HD];
        #pragma unroll
        for (int j4 = 0; j4 < HD; j4 += 4) {
            float4 hv = *(const float4*)&hr[j4];
            #pragma unroll
            for (int o = 0; o < 8; o++) {
                z[o] = fmaf(hv.x, sW1[(j4 + 0) * 8 + o], z[o]);
                z[o] = fmaf(hv.y, sW1[(j4 + 1) * 8 + o], z[o]);
                z[o] = fmaf(hv.z, sW1[(j4 + 2) * 8 + o], z[o]);
                z[o] = fmaf(hv.w, sW1[(j4 + 3) * 8 + o], z[o]);
            }
        }
        float z2 = lb2[0];
        #pragma unroll
        for (int o = 0; o < 8; o++) z2 += fmaxf(z[o], 0.f) * sW2[o];
        float p = 1.f / (1.f + expf(-z2));
        out_p[i] = p;

        float pm = (float)g_lsum * (1.0f / NN);
        float y = (float)labels[i];
        float w = y * (1.f - pm) + (1.f - y) * pm;
        float pc = fminf(fmaxf(p, 1e-7f), 1.f - 1e-7f);
        float bce = -(y * logf(pc) + (1.f - y) * logf(1.f - pc));
        term = w * bce;
    }
    #pragma unroll
    for (int off = 16; off; off >>= 1) term += __shfl_down_sync(0xffffffffu, term, off);
    if ((tid & 31) == 0) swsum[tid >> 5] = term;
    __syncthreads();
    if (tid == 0) {
        float s = 0.f;
        #pragma unroll
        for (int k2 = 0; k2 < 8; k2++) s += swsum[k2];
        atomicAdd(&g_loss, s);
    }
}

__global__ void k_final(float* __restrict__ out) {
    out[0] = g_loss * (1.0f / NN);
}

// ---------------- launch ----------------
extern "C" void kernel_launch(void* const* d_in, const int* in_sizes, int n_in,
                              void* d_out, int out_size) {
    const float* x      = (const float*)d_in[0];
    const int*   ei     = (const int*)d_in[1];
    const int*   labels = (const int*)d_in[2];
    const float* W1  = (const float*)d_in[3];
    const float* b1  = (const float*)d_in[4];
    const float* W2  = (const float*)d_in[5];
    const float* b2  = (const float*)d_in[6];
    const float* W3  = (const float*)d_in[7];
    const float* b3  = (const float*)d_in[8];
    const float* lW1 = (const float*)d_in[9];
    const float* lb1 = (const float*)d_in[10];
    const float* lW2 = (const float*)d_in[11];
    const float* lb2 = (const float*)d_in[12];

    float* out = (float*)d_out;
    int loss_elems = out_size - NN;
    float* out_p = out + (loss_elems > 0 ? loss_elems : 0);

    const int TPB = 256;
    const int NB_N = (NN + TPB - 1) / TPB;
    const int NB_E = (NE + TPB - 1) / TPB;
    const int agg_blocks  = NN / 16;   // 6250
    const int gemm_blocks = 592;

    k_init <<<NB_N, TPB>>>(labels);                         // 1
    k_count<<<NB_E, TPB>>>(ei);                             // 2
    k_scan <<<1, 1024>>>();                                 // 3 (dinv ready)
    k_gemm<NF, false><<<gemm_blocks, TPB>>>(x, W1);         // 4  <- profiled
    k_fill <<<NB_E, TPB>>>(ei);                             // 5
    k_agg<<<agg_blocks, TPB>>>(b1);                         // 6

    k_gemm<HD, true><<<gemm_blocks, TPB>>>(nullptr, W2);    // 7
    k_agg<<<agg_blocks, TPB>>>(b2);                         // 8

    k_gemm<HD, true><<<gemm_blocks, TPB>>>(nullptr, W3);    // 9
    k_agg<<<agg_blocks, TPB>>>(b3);                         // 10

    k_head<<<NB_N, TPB>>>(lW1, lb1, lW2, lb2, labels, out_p);  // 11
    if (loss_elems > 0) k_final<<<1, 1>>>(out);             // 12
}

// round 11
// speedup vs baseline: 1.5161x; 1.0302x over previous
#include <cuda_runtime.h>
#include <cstdint>

#define NN 100000
#define NE 1600000
#define NF 128
#define HD 64

// ---------------- scratch (no allocs allowed) ----------------
__device__ __align__(16) float g_dinv[NN];
__device__ __align__(16) float g_t  [NN * HD];   // (h @ W) * dinv[row]
__device__ __align__(16) float g_h  [NN * HD];   // layer output
__device__ int g_deg[NN];
__device__ int g_cursor[NN];
__device__ int g_rowstart[NN + 1];
__device__ int g_csr[NE];
__device__ float g_loss;
__device__ int   g_lsum;

// ---------------- 1: init ----------------
__global__ void k_init(const int* __restrict__ labels) {
    int i = blockIdx.x * blockDim.x + threadIdx.x;
    if (i == 0) { g_loss = 0.f; g_lsum = 0; }
    int v = 0;
    if (i < NN) { g_deg[i] = 0; v = labels[i]; }
    #pragma unroll
    for (int off = 16; off; off >>= 1) v += __shfl_down_sync(0xffffffffu, v, off);
    if ((threadIdx.x & 31) == 0 && v) atomicAdd(&g_lsum, v);
}

// ---------------- 2: histogram destinations ----------------
__global__ void k_count(const int* __restrict__ ei) {
    int e = blockIdx.x * blockDim.x + threadIdx.x;
    if (e < NE) {
        unsigned c = (unsigned)ei[NE + e];
        if (c < NN) atomicAdd(&g_deg[c], 1);
    }
}

// ---------------- 3: 1-block scan -> rowstart, cursor, dinv ----------------
__global__ void k_scan() {
    const int T = 1024;
    const int CH = (NN + T - 1) / T;
    __shared__ int sh[T];
    int tid = threadIdx.x;
    int lo = tid * CH, hi = lo + CH; if (hi > NN) hi = NN;
    int s = 0;
    for (int i = lo; i < hi; i++) s += g_deg[i];
    sh[tid] = s;
    __syncthreads();
    for (int off = 1; off < T; off <<= 1) {
        int v = (tid >= off) ? sh[tid - off] : 0;
        __syncthreads();
        sh[tid] += v;
        __syncthreads();
    }
    int run = sh[tid] - s;
    for (int i = lo; i < hi; i++) {
        int d = g_deg[i];
        g_rowstart[i] = run;
        g_cursor[i]   = run;
        g_dinv[i]     = rsqrtf((float)(d + 1));
        run += d;
    }
    if (tid == T - 1) g_rowstart[NN] = run;
}

// ---------------- GEMM: t[i,:] = (hin[i,:] @ W) * dinv[i] ----------------
// block 256 = 32 col-pairs x 8 row-threads (4 rows each); tile = 32 rows.
// (R10-proven retile: gemm1 = 64.6us)
template <int K, bool USEG>
__global__ void __launch_bounds__(256) k_gemm(const float* __restrict__ hin,
                                              const float* __restrict__ W) {
    __shared__ __align__(16) float  sW[K * HD];        // K=128: 32KB, K=64: 16KB
    __shared__ __align__(16) float4 srow[32][K / 4];   // K=128: 16KB, K=64: 8KB
    const float* src = USEG ? g_h : hin;
    int tid = threadIdx.x;
    for (int j = tid; j < K * HD / 4; j += 256)
        ((float4*)sW)[j] = ((const float4*)W)[j];

    int c2 = tid & 31;    // column pair: cols 2*c2, 2*c2+1
    int rt = tid >> 5;    // row-thread 0..7, owns rows rt*4..rt*4+3

    for (int rb = blockIdx.x * 32; rb < NN; rb += gridDim.x * 32) {
        __syncthreads();
        for (int j = tid; j < 32 * (K / 4); j += 256) {
            int r = j / (K / 4), kk = j % (K / 4);
            srow[r][kk] = ((const float4*)(src + (size_t)(rb + r) * K))[kk];
        }
        __syncthreads();

        float acc0[4], acc1[4];
        #pragma unroll
        for (int rr = 0; rr < 4; rr++) { acc0[rr] = 0.f; acc1[rr] = 0.f; }

        #pragma unroll
        for (int k4 = 0; k4 < K / 4; k4++) {
            float2 wa = *(const float2*)&sW[(4 * k4 + 0) * HD + 2 * c2];
            float2 wb = *(const float2*)&sW[(4 * k4 + 1) * HD + 2 * c2];
            float2 wc = *(const float2*)&sW[(4 * k4 + 2) * HD + 2 * c2];
            float2 wd = *(const float2*)&sW[(4 * k4 + 3) * HD + 2 * c2];
            #pragma unroll
            for (int rr = 0; rr < 4; rr++) {
                float4 h = srow[rt * 4 + rr][k4];   // warp-broadcast LDS.128
                acc0[rr] = fmaf(h.x, wa.x, acc0[rr]);
                acc0[rr] = fmaf(h.y, wb.x, acc0[rr]);
                acc0[rr] = fmaf(h.z, wc.x, acc0[rr]);
                acc0[rr] = fmaf(h.w, wd.x, acc0[rr]);
                acc1[rr] = fmaf(h.x, wa.y, acc1[rr]);
                acc1[rr] = fmaf(h.y, wb.y, acc1[rr]);
                acc1[rr] = fmaf(h.z, wc.y, acc1[rr]);
                acc1[rr] = fmaf(h.w, wd.y, acc1[rr]);
            }
        }
        #pragma unroll
        for (int rr = 0; rr < 4; rr++) {
            int gr = rb + rt * 4 + rr;
            float d = g_dinv[gr];
            float2 o = make_float2(acc0[rr] * d, acc1[rr] * d);
            *(float2*)&g_t[(size_t)gr * HD + 2 * c2] = o;
        }
    }
}

// ---------------- fill CSR ----------------
__global__ void k_fill(const int* __restrict__ ei) {
    int e = blockIdx.x * blockDim.x + threadIdx.x;
    if (e >= NE) return;
    unsigned src = (unsigned)ei[e];
    unsigned dst = (unsigned)ei[NE + e];
    if (src >= NN || dst >= NN) return;
    int pos = atomicAdd(&g_cursor[dst], 1);
    g_csr[pos] = (int)src;
}

// ---------------- agg + combine: h = relu(dinv[c]*(t[c]+sum t[src]) + b) ----
// 16 threads per node; unroll-4 with TWO independent accumulator chains
__global__ void k_agg(const float* __restrict__ b) {
    int tid  = threadIdx.x;
    int node = blockIdx.x * 16 + (tid >> 4);   // NN % 16 == 0
    int part = tid & 15;

    const float4* __restrict__ t4 = (const float4*)g_t;
    int s = g_rowstart[node];
    int e = g_rowstart[node + 1];

    float4 a0 = t4[(size_t)node * 16 + part];   // self loop
    float4 a1 = make_float4(0.f, 0.f, 0.f, 0.f);
    int i = s;
    for (; i + 4 <= e; i += 4) {
        int s0 = g_csr[i],     s1 = g_csr[i + 1];
        int s2 = g_csr[i + 2], s3 = g_csr[i + 3];
        float4 v0 = t4[(size_t)s0 * 16 + part];
        float4 v1 = t4[(size_t)s1 * 16 + part];
        float4 v2 = t4[(size_t)s2 * 16 + part];
        float4 v3 = t4[(size_t)s3 * 16 + part];
        a0.x += v0.x; a0.y += v0.y; a0.z += v0.z; a0.w += v0.w;
        a1.x += v1.x; a1.y += v1.y; a1.z += v1.z; a1.w += v1.w;
        a0.x += v2.x; a0.y += v2.y; a0.z += v2.z; a0.w += v2.w;
        a1.x += v3.x; a1.y += v3.y; a1.z += v3.z; a1.w += v3.w;
    }
    for (; i < e; i++) {
        float4 v = t4[(size_t)g_csr[i] * 16 + part];
        a0.x += v.x; a0.y += v.y; a0.z += v.z; a0.w += v.w;
    }
    float4 acc = make_float4(a0.x + a1.x, a0.y + a1.y, a0.z + a1.z, a0.w + a1.w);

    float d = g_dinv[node];
    float4 bb = *(const float4*)&b[part * 4];
    float4 o;
    o.x = fmaxf(fmaf(d, acc.x, bb.x), 0.f);
    o.y = fmaxf(fmaf(d, acc.y, bb.y), 0.f);
    o.z = fmaxf(fmaf(d, acc.z, bb.z), 0.f);
    o.w = fmaxf(fmaf(d, acc.w, bb.w), 0.f);
    ((float4*)g_h)[(size_t)node * 16 + part] = o;
}

// ---------------- MLP head + p output + weighted-BCE ----------------
__global__ void k_head(const float* __restrict__ lW1, const float* __restrict__ lb1,
                       const float* __restrict__ lW2, const float* __restrict__ lb2,
                       const int* __restrict__ labels, float* __restrict__ out_p) {
    __shared__ float sW1[HD * 8];
    __shared__ float sb1[8];
    __shared__ float sW2[8];
    __shared__ float swsum[8];
    int tid = threadIdx.x;
    for (int j = tid; j < HD * 8; j += 256) sW1[j] = lW1[j];
    if (tid < 8) { sb1[tid] = lb1[tid]; sW2[tid] = lW2[tid]; }
    __syncthreads();

    int i = blockIdx.x * 256 + tid;
    float term = 0.f;
    if (i < NN) {
        float z[8];
        #pragma unroll
        for (int o = 0; o < 8; o++) z[o] = sb1[o];
        const float* hr = &g_h[(size_t)i * HD];
        #pragma unroll
        for (int j4 = 0; j4 < HD; j4 += 4) {
            float4 hv = *(const float4*)&hr[j4];
            #pragma unroll
            for (int o = 0; o < 8; o++) {
                z[o] = fmaf(hv.x, sW1[(j4 + 0) * 8 + o], z[o]);
                z[o] = fmaf(hv.y, sW1[(j4 + 1) * 8 + o], z[o]);
                z[o] = fmaf(hv.z, sW1[(j4 + 2) * 8 + o], z[o]);
                z[o] = fmaf(hv.w, sW1[(j4 + 3) * 8 + o], z[o]);
            }
        }
        float z2 = lb2[0];
        #pragma unroll
        for (int o = 0; o < 8; o++) z2 += fmaxf(z[o], 0.f) * sW2[o];
        float p = 1.f / (1.f + expf(-z2));
        out_p[i] = p;

        float pm = (float)g_lsum * (1.0f / NN);
        float y = (float)labels[i];
        float w = y * (1.f - pm) + (1.f - y) * pm;
        float pc = fminf(fmaxf(p, 1e-7f), 1.f - 1e-7f);
        float bce = -(y * logf(pc) + (1.f - y) * logf(1.f - pc));
        term = w * bce;
    }
    #pragma unroll
    for (int off = 16; off; off >>= 1) term += __shfl_down_sync(0xffffffffu, term, off);
    if ((tid & 31) == 0) swsum[tid >> 5] = term;
    __syncthreads();
    if (tid == 0) {
        float s = 0.f;
        #pragma unroll
        for (int k2 = 0; k2 < 8; k2++) s += swsum[k2];
        atomicAdd(&g_loss, s);
    }
}

__global__ void k_final(float* __restrict__ out) {
    out[0] = g_loss * (1.0f / NN);
}

// ---------------- launch ----------------
extern "C" void kernel_launch(void* const* d_in, const int* in_sizes, int n_in,
                              void* d_out, int out_size) {
    const float* x      = (const float*)d_in[0];
    const int*   ei     = (const int*)d_in[1];
    const int*   labels = (const int*)d_in[2];
    const float* W1  = (const float*)d_in[3];
    const float* b1  = (const float*)d_in[4];
    const float* W2  = (const float*)d_in[5];
    const float* b2  = (const float*)d_in[6];
    const float* W3  = (const float*)d_in[7];
    const float* b3  = (const float*)d_in[8];
    const float* lW1 = (const float*)d_in[9];
    const float* lb1 = (const float*)d_in[10];
    const float* lW2 = (const float*)d_in[11];
    const float* lb2 = (const float*)d_in[12];

    float* out = (float*)d_out;
    int loss_elems = out_size - NN;
    float* out_p = out + (loss_elems > 0 ? loss_elems : 0);

    const int TPB = 256;
    const int NB_N = (NN + TPB - 1) / TPB;
    const int NB_E = (NE + TPB - 1) / TPB;
    const int agg_blocks  = NN / 16;   // 6250
    const int gemm_blocks = 592;

    k_init <<<NB_N, TPB>>>(labels);                         // 1
    k_count<<<NB_E, TPB>>>(ei);                             // 2
    k_scan <<<1, 1024>>>();                                 // 3 (dinv ready)
    k_gemm<NF, false><<<gemm_blocks, TPB>>>(x, W1);         // 4  <- profiled
    k_fill <<<NB_E, TPB>>>(ei);                             // 5
    k_agg<<<agg_blocks, TPB>>>(b1);                         // 6

    k_gemm<HD, true><<<gemm_blocks, TPB>>>(nullptr, W2);    // 7
    k_agg<<<agg_blocks, TPB>>>(b2);                         // 8

    k_gemm<HD, true><<<gemm_blocks, TPB>>>(nullptr, W3);    // 9
    k_agg<<<agg_blocks, TPB>>>(b3);                         // 10

    k_head<<<NB_N, TPB>>>(lW1, lb1, lW2, lb2, labels, out_p);  // 11
    if (loss_elems > 0) k_final<<<1, 1>>>(out);             // 12
}